// round 1
// baseline (speedup 1.0000x reference)
#include <cuda_runtime.h>

#define NN 50000
#define EE 800000
#define BB 2
#define DD 64
#define HH 4
#define dHEAD 16
#define OO 64
#define BH 8           // B*H
#define NB (NN*BB)

// Scratch (allocation-free rule: __device__ globals)
__device__ float g_feat[NN*BB*HH*dHEAD];   // [(n*2+b)*64 + h*16+k]  = [(n*8+bh)*16+k]
__device__ float g_el[NN*BB*HH];           // [n*8 + bh]
__device__ float g_er[NN*BB*HH];
__device__ float g_emax[NN*BB*HH];
__device__ float g_denom[NN*BB*HH];
__device__ float g_rst[NN*BB*HH*dHEAD];    // unnormalized sum(ex * feat[src])

// ---------------------------------------------------------------------------
// K1: feat = x @ W_fc.T (per (b,n) row), plus el/er head dot-products
// 256 threads = 4 rows/block, W_fc cached in shared (padded vs bank conflicts)
// ---------------------------------------------------------------------------
__global__ void k_feat(const float* __restrict__ x, const float* __restrict__ Wfc,
                       const float* __restrict__ al, const float* __restrict__ ar) {
    __shared__ float sW[64][65];
    __shared__ float sx[4][64];
    __shared__ float sal[64], sar[64];
    int tid = threadIdx.x;
    for (int i = tid; i < 64*64; i += 256) sW[i >> 6][i & 63] = Wfc[i];
    if (tid < 64) { sal[tid] = al[tid]; sar[tid] = ar[tid]; }
    int row = tid >> 6;
    int k   = tid & 63;
    int r = blockIdx.x * 4 + row;          // r = b*N + n  (x is [B,N,D])
    sx[row][k] = x[r * 64 + k];
    __syncthreads();

    float s = 0.f;
    #pragma unroll
    for (int j = 0; j < 64; j++) s += sx[row][j] * sW[k][j];

    int n = r % NN, b = r / NN;
    int gr = n * 2 + b;                    // node-major layout for edge gathers
    g_feat[gr * 64 + k] = s;

    float vl = s * sal[k];
    float vr = s * sar[k];
    #pragma unroll
    for (int off = 8; off; off >>= 1) {
        vl += __shfl_down_sync(0xffffffffu, vl, off, 16);
        vr += __shfl_down_sync(0xffffffffu, vr, off, 16);
    }
    if ((k & 15) == 0) {
        int h = k >> 4;
        g_el[gr * 4 + h] = vl;
        g_er[gr * 4 + h] = vr;
    }
}

// ---------------------------------------------------------------------------
// K2: init scratch
// ---------------------------------------------------------------------------
__global__ void k_init() {
    int i = blockIdx.x * blockDim.x + threadIdx.x;
    if (i < NN*BB*HH*dHEAD) g_rst[i] = 0.f;
    if (i < NN*BB*HH) { g_emax[i] = -3.0e38f; g_denom[i] = 0.f; }
}

// float atomic max via signed-max / unsigned-min trick
__device__ __forceinline__ void atomicMaxF(float* a, float v) {
    if (v >= 0.f) atomicMax((int*)a, __float_as_int(v));
    else          atomicMin((unsigned int*)a, __float_as_uint(v));
}

// ---------------------------------------------------------------------------
// K3: segment max of edge scores over dst. 1 thread / edge, 8 (b,h) combos.
// ---------------------------------------------------------------------------
__global__ void k_edge_max(const int* __restrict__ src, const int* __restrict__ dst,
                           const float* __restrict__ w) {
    int e = blockIdx.x * blockDim.x + threadIdx.x;
    if (e >= EE) return;
    int s = src[e], t = dst[e];
    float we = w[e];
    const float4* pl = (const float4*)&g_el[s * 8];
    const float4* pr = (const float4*)&g_er[t * 8];
    float4 l0 = pl[0], l1 = pl[1];
    float4 r0 = pr[0], r1 = pr[1];
    float sc[8] = { l0.x + r0.x, l0.y + r0.y, l0.z + r0.z, l0.w + r0.w,
                    l1.x + r1.x, l1.y + r1.y, l1.z + r1.z, l1.w + r1.w };
    #pragma unroll
    for (int i = 0; i < 8; i++) {
        float v = sc[i];
        v = (v > 0.f) ? v : 0.1f * v;      // LeakyReLU(0.1)
        v *= we;
        atomicMaxF(&g_emax[t * 8 + i], v);
    }
}

// ---------------------------------------------------------------------------
// K4: fused exp-sum + unnormalized aggregation. 1 thread / (edge, b, h).
// denom[t] += ex ;  rst[t] += ex * feat[s]
// ---------------------------------------------------------------------------
__global__ void k_edge_sum(const int* __restrict__ src, const int* __restrict__ dst,
                           const float* __restrict__ w) {
    int gid = blockIdx.x * blockDim.x + threadIdx.x;
    if (gid >= EE * BH) return;
    int e = gid >> 3, bh = gid & 7;
    int s = src[e], t = dst[e];
    float sc = g_el[s * 8 + bh] + g_er[t * 8 + bh];
    sc = (sc > 0.f) ? sc : 0.1f * sc;
    sc *= w[e];
    float ex = __expf(sc - g_emax[t * 8 + bh]);
    atomicAdd(&g_denom[t * 8 + bh], ex);
    const float4* fp = (const float4*)&g_feat[(s * 8 + bh) * 16];
    float* rp = &g_rst[(t * 8 + bh) * 16];
    #pragma unroll
    for (int q = 0; q < 4; q++) {
        float4 f = fp[q];
        atomicAdd(rp + q * 4 + 0, ex * f.x);
        atomicAdd(rp + q * 4 + 1, ex * f.y);
        atomicAdd(rp + q * 4 + 2, ex * f.z);
        atomicAdd(rp + q * 4 + 3, ex * f.w);
    }
}

// ---------------------------------------------------------------------------
// K5: out[b,n,h,o] = (rst[n,b,h,:]/denom[n,b,h]) @ W_out.T + b_out
// ---------------------------------------------------------------------------
__global__ void k_out(const float* __restrict__ Wout, const float* __restrict__ bout,
                      float* __restrict__ out) {
    __shared__ float sWo[64 * 16];
    __shared__ float sb[64];
    int tid = threadIdx.x;
    for (int i = tid; i < 64 * 16; i += 256) sWo[i] = Wout[i];
    if (tid < 64) sb[tid] = bout[tid];
    __syncthreads();
    int gid = blockIdx.x * 256 + tid;
    if (gid >= BB * NN * HH * OO) return;
    int o = gid & 63;
    int h = (gid >> 6) & 3;
    int n = (gid >> 8) % NN;
    int b = gid / (NN * 256);
    int bi = n * 8 + b * 4 + h;
    float den = g_denom[bi];
    float inv = (den > 0.f) ? 1.f / den : 0.f;   // empty segment -> b_out
    const float4* rp = (const float4*)&g_rst[bi * 16];
    const float4* wp = (const float4*)&sWo[o * 16];
    float acc = 0.f;
    #pragma unroll
    for (int q = 0; q < 4; q++) {
        float4 rv = rp[q]; float4 wv = wp[q];
        acc += rv.x * wv.x + rv.y * wv.y + rv.z * wv.z + rv.w * wv.w;
    }
    out[gid] = acc * inv + sb[o];
}

// ---------------------------------------------------------------------------
// inputs (metadata order): vt, x, w, src, dst, W_fc, attn_l, attn_r, W_out, b_out
// ---------------------------------------------------------------------------
extern "C" void kernel_launch(void* const* d_in, const int* in_sizes, int n_in,
                              void* d_out, int out_size) {
    const float* x    = (const float*)d_in[1];
    const float* w    = (const float*)d_in[2];
    const int*   src  = (const int*)  d_in[3];
    const int*   dst  = (const int*)  d_in[4];
    const float* Wfc  = (const float*)d_in[5];
    const float* al   = (const float*)d_in[6];
    const float* ar   = (const float*)d_in[7];
    const float* Wout = (const float*)d_in[8];
    const float* bout = (const float*)d_in[9];
    float* out = (float*)d_out;

    k_feat<<<NB / 4, 256>>>(x, Wfc, al, ar);
    k_init<<<(NN * BB * HH * dHEAD + 255) / 256, 256>>>();
    k_edge_max<<<(EE + 255) / 256, 256>>>(src, dst, w);
    k_edge_sum<<<(EE * BH + 255) / 256, 256>>>(src, dst, w);
    k_out<<<(BB * NN * HH * OO + 255) / 256, 256>>>(Wout, bout, out);
}

// round 2
// speedup vs baseline: 1.6916x; 1.6916x over previous
#include <cuda_runtime.h>

#define NN 50000
#define EE 800000
#define BB 2
#define BH 8
#define NB (NN*BB)
#define SCAN_B 1024
#define NBLK ((NN + SCAN_B - 1) / SCAN_B)   // 49

// -------- scratch (__device__ globals; no allocation allowed) --------
__device__ float g_feat[NN*BB*64];     // [(n*2+b)*64 + h*16+k]
__device__ float g_el[NN*BB*4];        // [n*8 + b*4 + h]
__device__ float g_er[NN*BB*4];
__device__ float g_denom[NN*BB*4];
__device__ float g_rst[NN*BB*64];      // unnormalized aggregate
__device__ int   g_deg[NN];
__device__ int   g_off[NN + 1];
__device__ int   g_cursor[NN];
__device__ int   g_bsum[NBLK];
__device__ int   g_esrc[EE];           // dst-sorted edge src
__device__ float g_ew[EE];             // dst-sorted edge weight

// ---------------------------------------------------------------------------
// K1: feat = x @ W_fc.T, plus el/er head dot-products
// ---------------------------------------------------------------------------
__global__ void k_feat(const float* __restrict__ x, const float* __restrict__ Wfc,
                       const float* __restrict__ al, const float* __restrict__ ar) {
    __shared__ float sW[64][65];
    __shared__ float sx[4][64];
    __shared__ float sal[64], sar[64];
    int tid = threadIdx.x;
    for (int i = tid; i < 64*64; i += 256) sW[i >> 6][i & 63] = Wfc[i];
    if (tid < 64) { sal[tid] = al[tid]; sar[tid] = ar[tid]; }
    int row = tid >> 6;
    int k   = tid & 63;
    int r = blockIdx.x * 4 + row;           // r = b*N + n
    sx[row][k] = x[r * 64 + k];
    __syncthreads();

    float s = 0.f;
    #pragma unroll
    for (int j = 0; j < 64; j++) s += sx[row][j] * sW[k][j];

    int n = r % NN, b = r / NN;
    int gr = n * 2 + b;
    g_feat[gr * 64 + k] = s;

    float vl = s * sal[k];
    float vr = s * sar[k];
    #pragma unroll
    for (int off = 8; off; off >>= 1) {
        vl += __shfl_down_sync(0xffffffffu, vl, off, 16);
        vr += __shfl_down_sync(0xffffffffu, vr, off, 16);
    }
    if ((k & 15) == 0) {
        int h = k >> 4;
        g_el[gr * 4 + h] = vl;
        g_er[gr * 4 + h] = vr;
    }
}

// ---------------------------------------------------------------------------
// CSR build: zero histogram -> count -> hierarchical exclusive scan -> scatter
// ---------------------------------------------------------------------------
__global__ void k_zero_deg() {
    int i = blockIdx.x * blockDim.x + threadIdx.x;
    if (i < NN) g_deg[i] = 0;
}

__global__ void k_count(const int* __restrict__ dst) {
    int e = blockIdx.x * blockDim.x + threadIdx.x;
    if (e < EE) atomicAdd(&g_deg[dst[e]], 1);
}

__global__ void k_scan1() {   // per-block inclusive scan -> exclusive out + block sums
    __shared__ int s[SCAN_B];
    int tid = threadIdx.x;
    int i = blockIdx.x * SCAN_B + tid;
    int v = (i < NN) ? g_deg[i] : 0;
    s[tid] = v;
    __syncthreads();
    #pragma unroll
    for (int off = 1; off < SCAN_B; off <<= 1) {
        int t = (tid >= off) ? s[tid - off] : 0;
        __syncthreads();
        s[tid] += t;
        __syncthreads();
    }
    if (i < NN) g_off[i] = s[tid] - v;        // exclusive within block
    if (tid == SCAN_B - 1) g_bsum[blockIdx.x] = s[tid];
}

__global__ void k_scan2() {   // scan the 49 block sums (single warp-ish block)
    __shared__ int s[64];
    int tid = threadIdx.x;
    int v = (tid < NBLK) ? g_bsum[tid] : 0;
    s[tid] = v;
    __syncthreads();
    #pragma unroll
    for (int off = 1; off < 64; off <<= 1) {
        int t = (tid >= off) ? s[tid - off] : 0;
        __syncthreads();
        s[tid] += t;
        __syncthreads();
    }
    if (tid < NBLK) g_bsum[tid] = s[tid] - v; // exclusive
    if (tid == 0) g_off[NN] = EE;
}

__global__ void k_scan3() {   // add block offsets, init cursors
    int i = blockIdx.x * blockDim.x + threadIdx.x;
    if (i < NN) {
        int o = g_off[i] + g_bsum[i / SCAN_B];
        g_off[i] = o;
        g_cursor[i] = o;
    }
}

__global__ void k_scatter(const int* __restrict__ src, const int* __restrict__ dst,
                          const float* __restrict__ w) {
    int e = blockIdx.x * blockDim.x + threadIdx.x;
    if (e >= EE) return;
    int t = dst[e];
    int pos = atomicAdd(&g_cursor[t], 1);
    g_esrc[pos] = src[e];
    g_ew[pos]  = w[e];
}

// ---------------------------------------------------------------------------
// K_agg: one warp per (node, b). Online softmax + register aggregation.
// Lane owns elements j=lane and j+32 of the 64-wide (h,k) vector; h = j/16.
// ---------------------------------------------------------------------------
__global__ void k_agg() {
    int wb = (blockIdx.x * 256 + threadIdx.x) >> 5;   // global warp id
    if (wb >= NB) return;
    int lane = threadIdx.x & 31;
    int n = wb >> 1, b = wb & 1;
    int h0 = lane >> 4;          // 0 or 1
    int h1 = h0 + 2;             // 2 or 3
    int ebase = n * 8 + b * 4;

    float er0 = g_er[ebase + h0];
    float er1 = g_er[ebase + h1];

    int beg = g_off[n], end = g_off[n + 1];

    float m0 = -3.0e38f, m1 = -3.0e38f;
    float d0 = 0.f, d1 = 0.f;
    float a0 = 0.f, a1 = 0.f;

    for (int e = beg; e < end; e++) {
        int   s  = __ldg(&g_esrc[e]);
        float we = __ldg(&g_ew[e]);
        int sb = s * 8 + b * 4;
        float sc0 = g_el[sb + h0] + er0;
        float sc1 = g_el[sb + h1] + er1;
        sc0 = (sc0 > 0.f) ? sc0 : 0.1f * sc0;
        sc1 = (sc1 > 0.f) ? sc1 : 0.1f * sc1;
        sc0 *= we; sc1 *= we;

        if (sc0 > m0) {
            float r = __expf(m0 - sc0);
            d0 *= r; a0 *= r; m0 = sc0;
        }
        if (sc1 > m1) {
            float r = __expf(m1 - sc1);
            d1 *= r; a1 *= r; m1 = sc1;
        }
        float ex0 = __expf(sc0 - m0);
        float ex1 = __expf(sc1 - m1);
        const float* fp = &g_feat[(s * 2 + b) * 64];
        float f0 = __ldg(fp + lane);
        float f1 = __ldg(fp + 32 + lane);
        d0 += ex0; d1 += ex1;
        a0 += ex0 * f0;
        a1 += ex1 * f1;
    }

    float* rp = &g_rst[(n * 2 + b) * 64];
    rp[lane]      = a0;
    rp[32 + lane] = a1;
    if ((lane & 15) == 0) {
        g_denom[ebase + h0] = d0;
        g_denom[ebase + h1] = d1;
    }
}

// ---------------------------------------------------------------------------
// K_out: out[b,n,h,o] = (rst/denom) @ W_out.T + b_out
// ---------------------------------------------------------------------------
__global__ void k_out(const float* __restrict__ Wout, const float* __restrict__ bout,
                      float* __restrict__ out) {
    __shared__ float sWo[64 * 16];
    __shared__ float sb[64];
    int tid = threadIdx.x;
    for (int i = tid; i < 64 * 16; i += 256) sWo[i] = Wout[i];
    if (tid < 64) sb[tid] = bout[tid];
    __syncthreads();
    int gid = blockIdx.x * 256 + tid;
    if (gid >= BB * NN * 4 * 64) return;
    int o = gid & 63;
    int h = (gid >> 6) & 3;
    int n = (gid >> 8) % NN;
    int b = gid / (NN * 256);
    int bi = n * 8 + b * 4 + h;
    float den = g_denom[bi];
    float inv = (den > 0.f) ? 1.f / den : 0.f;
    const float4* rp = (const float4*)&g_rst[bi * 16];
    const float4* wp = (const float4*)&sWo[o * 16];
    float acc = 0.f;
    #pragma unroll
    for (int q = 0; q < 4; q++) {
        float4 rv = rp[q]; float4 wv = wp[q];
        acc += rv.x * wv.x + rv.y * wv.y + rv.z * wv.z + rv.w * wv.w;
    }
    out[gid] = acc * inv + sb[o];
}

// ---------------------------------------------------------------------------
// inputs: vt, x, w, src, dst, W_fc, attn_l, attn_r, W_out, b_out
// ---------------------------------------------------------------------------
extern "C" void kernel_launch(void* const* d_in, const int* in_sizes, int n_in,
                              void* d_out, int out_size) {
    const float* x    = (const float*)d_in[1];
    const float* w    = (const float*)d_in[2];
    const int*   src  = (const int*)  d_in[3];
    const int*   dst  = (const int*)  d_in[4];
    const float* Wfc  = (const float*)d_in[5];
    const float* al   = (const float*)d_in[6];
    const float* ar   = (const float*)d_in[7];
    const float* Wout = (const float*)d_in[8];
    const float* bout = (const float*)d_in[9];
    float* out = (float*)d_out;

    k_feat<<<NB / 4, 256>>>(x, Wfc, al, ar);
    k_zero_deg<<<(NN + 255) / 256, 256>>>();
    k_count<<<(EE + 255) / 256, 256>>>(dst);
    k_scan1<<<NBLK, SCAN_B>>>();
    k_scan2<<<1, 64>>>();
    k_scan3<<<(NN + 255) / 256, 256>>>();
    k_scatter<<<(EE + 255) / 256, 256>>>(src, dst, w);
    k_agg<<<(NB * 32 + 255) / 256, 256>>>();
    k_out<<<(BB * NN * 4 * 64 + 255) / 256, 256>>>(Wout, bout, out);
}

// round 3
// speedup vs baseline: 2.7513x; 1.6264x over previous
#include <cuda_runtime.h>

#define NN 50000
#define EE 800000
#define BB 2
#define NB (NN*BB)
#define SCAN_B 1024
#define NBLK ((NN + SCAN_B - 1) / SCAN_B)   // 49

// -------- scratch (__device__ globals; no allocation allowed) --------
__device__ float  g_feat[NN*BB*64];    // [(n*2+b)*64 + h*16+k]
__device__ float  g_el[NN*BB*4];       // [n*8 + b*4 + h]
__device__ float  g_er[NN*BB*4];
__device__ int    g_deg[NN];
__device__ int    g_off[NN + 1];
__device__ int    g_cursor[NN];
__device__ int    g_bsum[NBLK];
__device__ float2 g_edge[EE];          // dst-sorted: (.x = src bits, .y = w)

// ---------------------------------------------------------------------------
// K1: feat = x @ W_fc.T, plus el/er head dot-products
// ---------------------------------------------------------------------------
__global__ void k_feat(const float* __restrict__ x, const float* __restrict__ Wfc,
                       const float* __restrict__ al, const float* __restrict__ ar) {
    __shared__ float sW[64][65];
    __shared__ float sx[4][64];
    __shared__ float sal[64], sar[64];
    int tid = threadIdx.x;
    for (int i = tid; i < 64*64; i += 256) sW[i >> 6][i & 63] = Wfc[i];
    if (tid < 64) { sal[tid] = al[tid]; sar[tid] = ar[tid]; }
    int row = tid >> 6;
    int k   = tid & 63;
    int r = blockIdx.x * 4 + row;           // r = b*N + n
    sx[row][k] = x[r * 64 + k];
    __syncthreads();

    float s = 0.f;
    #pragma unroll
    for (int j = 0; j < 64; j++) s += sx[row][j] * sW[k][j];

    int n = r % NN, b = r / NN;
    int gr = n * 2 + b;
    g_feat[gr * 64 + k] = s;

    float vl = s * sal[k];
    float vr = s * sar[k];
    #pragma unroll
    for (int off = 8; off; off >>= 1) {
        vl += __shfl_down_sync(0xffffffffu, vl, off, 16);
        vr += __shfl_down_sync(0xffffffffu, vr, off, 16);
    }
    if ((k & 15) == 0) {
        int h = k >> 4;
        g_el[(n * 2 + b) * 4 + h] = 0.f;    // placeholder overwritten below
        g_el[gr * 4 + h] = vl;              // NOTE: layout [n*8 + b*4 + h] == [(n*2+b)*4+h]
        g_er[gr * 4 + h] = vr;
    }
}

// ---------------------------------------------------------------------------
// CSR build
// ---------------------------------------------------------------------------
__global__ void k_zero_deg() {
    int i = blockIdx.x * blockDim.x + threadIdx.x;
    if (i < NN) g_deg[i] = 0;
}

__global__ void k_count(const int* __restrict__ dst) {
    int e = blockIdx.x * blockDim.x + threadIdx.x;
    if (e < EE) atomicAdd(&g_deg[dst[e]], 1);
}

__global__ void k_scan1() {
    __shared__ int s[SCAN_B];
    int tid = threadIdx.x;
    int i = blockIdx.x * SCAN_B + tid;
    int v = (i < NN) ? g_deg[i] : 0;
    s[tid] = v;
    __syncthreads();
    #pragma unroll
    for (int off = 1; off < SCAN_B; off <<= 1) {
        int t = (tid >= off) ? s[tid - off] : 0;
        __syncthreads();
        s[tid] += t;
        __syncthreads();
    }
    if (i < NN) g_off[i] = s[tid] - v;
    if (tid == SCAN_B - 1) g_bsum[blockIdx.x] = s[tid];
}

__global__ void k_scan2() {
    __shared__ int s[64];
    int tid = threadIdx.x;
    int v = (tid < NBLK) ? g_bsum[tid] : 0;
    s[tid] = v;
    __syncthreads();
    #pragma unroll
    for (int off = 1; off < 64; off <<= 1) {
        int t = (tid >= off) ? s[tid - off] : 0;
        __syncthreads();
        s[tid] += t;
        __syncthreads();
    }
    if (tid < NBLK) g_bsum[tid] = s[tid] - v;
    if (tid == 0) g_off[NN] = EE;
}

__global__ void k_scan3() {
    int i = blockIdx.x * blockDim.x + threadIdx.x;
    if (i < NN) {
        int o = g_off[i] + g_bsum[i / SCAN_B];
        g_off[i] = o;
        g_cursor[i] = o;
    }
}

__global__ void k_scatter(const int* __restrict__ src, const int* __restrict__ dst,
                          const float* __restrict__ w) {
    int e = blockIdx.x * blockDim.x + threadIdx.x;
    if (e >= EE) return;
    int t = dst[e];
    int pos = atomicAdd(&g_cursor[t], 1);
    g_edge[pos] = make_float2(__int_as_float(src[e]), w[e]);
}

// ---------------------------------------------------------------------------
// K_agg_out: one warp per node, BOTH batches. Online softmax + register
// aggregation, fused output projection (W_out rows lane / lane+32 in regs).
// Element layout per batch: lane owns feat[lane] (head h0=lane/16) and
// feat[lane+32] (head h1=h0+2).
// ---------------------------------------------------------------------------
__global__ void __launch_bounds__(256) k_agg_out(
        const float* __restrict__ Wout, const float* __restrict__ bout,
        float* __restrict__ out) {
    __shared__ float sA[8][128];           // per-warp normalized [b*64 + elem]
    int warp = threadIdx.x >> 5;
    int lane = threadIdx.x & 31;
    int n = blockIdx.x * 8 + warp;
    if (n >= NN) return;

    // W_out rows for this lane's two output columns
    float4 wA[4], wB[4];
    #pragma unroll
    for (int q = 0; q < 4; q++) {
        wA[q] = ((const float4*)&Wout[lane * 16])[q];
        wB[q] = ((const float4*)&Wout[(lane + 32) * 16])[q];
    }
    float bias0 = bout[lane], bias1 = bout[lane + 32];

    int h0sel = lane >> 4;                 // 0 or 1
    // er for (b0,h0),(b0,h1),(b1,h0),(b1,h1)
    float4 e0 = *(const float4*)&g_er[n * 8];
    float4 e1 = *(const float4*)&g_er[n * 8 + 4];
    float er00 = h0sel ? e0.y : e0.x;
    float er01 = h0sel ? e0.w : e0.z;
    float er10 = h0sel ? e1.y : e1.x;
    float er11 = h0sel ? e1.w : e1.z;

    int beg = g_off[n], end = g_off[n + 1];

    float m00 = -3.0e38f, m01 = -3.0e38f, m10 = -3.0e38f, m11 = -3.0e38f;
    float d00 = 0.f, d01 = 0.f, d10 = 0.f, d11 = 0.f;
    float a0 = 0.f, a1 = 0.f, a2 = 0.f, a3 = 0.f;

    float2 cur;
    if (beg < end) cur = __ldg(&g_edge[beg]);
    for (int e = beg; e < end; e++) {
        float2 nxt;
        if (e + 1 < end) nxt = __ldg(&g_edge[e + 1]);
        int   s  = __float_as_int(cur.x);
        float we = cur.y;
        cur = nxt;

        const float4* lp = (const float4*)&g_el[s * 8];
        float4 l0 = __ldg(lp), l1 = __ldg(lp + 1);
        float sc00 = (h0sel ? l0.y : l0.x) + er00;
        float sc01 = (h0sel ? l0.w : l0.z) + er01;
        float sc10 = (h0sel ? l1.y : l1.x) + er10;
        float sc11 = (h0sel ? l1.w : l1.z) + er11;
        sc00 = ((sc00 > 0.f) ? sc00 : 0.1f * sc00) * we;
        sc01 = ((sc01 > 0.f) ? sc01 : 0.1f * sc01) * we;
        sc10 = ((sc10 > 0.f) ? sc10 : 0.1f * sc10) * we;
        sc11 = ((sc11 > 0.f) ? sc11 : 0.1f * sc11) * we;

        const float* fp = &g_feat[s * 128];
        float f0 = __ldg(fp + lane);
        float f1 = __ldg(fp + 32 + lane);
        float f2 = __ldg(fp + 64 + lane);
        float f3 = __ldg(fp + 96 + lane);

        if (sc00 > m00) { float r = __expf(m00 - sc00); d00 *= r; a0 *= r; m00 = sc00; }
        if (sc01 > m01) { float r = __expf(m01 - sc01); d01 *= r; a1 *= r; m01 = sc01; }
        if (sc10 > m10) { float r = __expf(m10 - sc10); d10 *= r; a2 *= r; m10 = sc10; }
        if (sc11 > m11) { float r = __expf(m11 - sc11); d11 *= r; a3 *= r; m11 = sc11; }
        float x00 = __expf(sc00 - m00);
        float x01 = __expf(sc01 - m01);
        float x10 = __expf(sc10 - m10);
        float x11 = __expf(sc11 - m11);
        d00 += x00; d01 += x01; d10 += x10; d11 += x11;
        a0 += x00 * f0; a1 += x01 * f1; a2 += x10 * f2; a3 += x11 * f3;
    }

    float i00 = (d00 > 0.f) ? 1.f / d00 : 0.f;
    float i01 = (d01 > 0.f) ? 1.f / d01 : 0.f;
    float i10 = (d10 > 0.f) ? 1.f / d10 : 0.f;
    float i11 = (d11 > 0.f) ? 1.f / d11 : 0.f;
    sA[warp][lane]      = a0 * i00;
    sA[warp][32 + lane] = a1 * i01;
    sA[warp][64 + lane] = a2 * i10;
    sA[warp][96 + lane] = a3 * i11;
    __syncwarp();

    // out[b][n][h][o], o in {lane, lane+32}
    #pragma unroll
    for (int b = 0; b < 2; b++) {
        #pragma unroll
        for (int h = 0; h < 4; h++) {
            const float4* ap = (const float4*)&sA[warp][b * 64 + h * 16];
            float acc0 = bias0, acc1 = bias1;
            #pragma unroll
            for (int q = 0; q < 4; q++) {
                float4 av = ap[q];
                acc0 += av.x * wA[q].x + av.y * wA[q].y + av.z * wA[q].z + av.w * wA[q].w;
                acc1 += av.x * wB[q].x + av.y * wB[q].y + av.z * wB[q].z + av.w * wB[q].w;
            }
            float* op = &out[((b * NN + n) * 4 + h) * 64];
            op[lane]      = acc0;
            op[lane + 32] = acc1;
        }
    }
}

// ---------------------------------------------------------------------------
// inputs: vt, x, w, src, dst, W_fc, attn_l, attn_r, W_out, b_out
// ---------------------------------------------------------------------------
extern "C" void kernel_launch(void* const* d_in, const int* in_sizes, int n_in,
                              void* d_out, int out_size) {
    const float* x    = (const float*)d_in[1];
    const float* w    = (const float*)d_in[2];
    const int*   src  = (const int*)  d_in[3];
    const int*   dst  = (const int*)  d_in[4];
    const float* Wfc  = (const float*)d_in[5];
    const float* al   = (const float*)d_in[6];
    const float* ar   = (const float*)d_in[7];
    const float* Wout = (const float*)d_in[8];
    const float* bout = (const float*)d_in[9];
    float* out = (float*)d_out;

    k_feat<<<NB / 4, 256>>>(x, Wfc, al, ar);
    k_zero_deg<<<(NN + 255) / 256, 256>>>();
    k_count<<<(EE + 255) / 256, 256>>>(dst);
    k_scan1<<<NBLK, SCAN_B>>>();
    k_scan2<<<1, 64>>>();
    k_scan3<<<(NN + 255) / 256, 256>>>();
    k_scatter<<<(EE + 255) / 256, 256>>>(src, dst, w);
    k_agg_out<<<(NN + 7) / 8, 256>>>(Wout, bout, out);
}

// round 4
// speedup vs baseline: 3.3684x; 1.2243x over previous
#include <cuda_runtime.h>

#define NN 50000
#define EE 800000
#define BB 2
#define NB (NN*BB)
#define SCAN_B 1024
#define NBLK ((NN + SCAN_B - 1) / SCAN_B)   // 49

// -------- scratch (__device__ globals; no allocation allowed) --------
__device__ float  g_feat[NN*BB*64];    // [(n*2+b)*64 + h*16+k]
__device__ float  g_el[NN*BB*4];       // [(n*2+b)*4 + h]
__device__ float  g_er[NN*BB*4];
__device__ int    g_deg[NN];
__device__ int    g_off[NN + 1];
__device__ int    g_cursor[NN];
__device__ int    g_bsum[NBLK];
__device__ float2 g_edge[EE];          // dst-sorted: (.x = src bits, .y = w)

// ---------------------------------------------------------------------------
// K1: feat = x @ W_fc.T, plus el/er head dot-products
// ---------------------------------------------------------------------------
__global__ void k_feat(const float* __restrict__ x, const float* __restrict__ Wfc,
                       const float* __restrict__ al, const float* __restrict__ ar) {
    __shared__ float sW[64][65];
    __shared__ float sx[4][64];
    __shared__ float sal[64], sar[64];
    int tid = threadIdx.x;
    for (int i = tid; i < 64*64; i += 256) sW[i >> 6][i & 63] = Wfc[i];
    if (tid < 64) { sal[tid] = al[tid]; sar[tid] = ar[tid]; }
    int row = tid >> 6;
    int k   = tid & 63;
    int r = blockIdx.x * 4 + row;           // r = b*N + n
    sx[row][k] = x[r * 64 + k];
    __syncthreads();

    float s = 0.f;
    #pragma unroll
    for (int j = 0; j < 64; j++) s += sx[row][j] * sW[k][j];

    int n = r % NN, b = r / NN;
    int gr = n * 2 + b;
    g_feat[gr * 64 + k] = s;

    float vl = s * sal[k];
    float vr = s * sar[k];
    #pragma unroll
    for (int off = 8; off; off >>= 1) {
        vl += __shfl_down_sync(0xffffffffu, vl, off, 16);
        vr += __shfl_down_sync(0xffffffffu, vr, off, 16);
    }
    if ((k & 15) == 0) {
        int h = k >> 4;
        g_el[gr * 4 + h] = vl;
        g_er[gr * 4 + h] = vr;
    }
}

// ---------------------------------------------------------------------------
// CSR build
// ---------------------------------------------------------------------------
__global__ void k_zero_deg() {
    int i = blockIdx.x * blockDim.x + threadIdx.x;
    if (i < NN) g_deg[i] = 0;
}

__global__ void k_count(const int* __restrict__ dst) {
    int e = blockIdx.x * blockDim.x + threadIdx.x;
    if (e < EE) atomicAdd(&g_deg[dst[e]], 1);
}

__global__ void k_scan1() {
    __shared__ int s[SCAN_B];
    int tid = threadIdx.x;
    int i = blockIdx.x * SCAN_B + tid;
    int v = (i < NN) ? g_deg[i] : 0;
    s[tid] = v;
    __syncthreads();
    #pragma unroll
    for (int off = 1; off < SCAN_B; off <<= 1) {
        int t = (tid >= off) ? s[tid - off] : 0;
        __syncthreads();
        s[tid] += t;
        __syncthreads();
    }
    if (i < NN) g_off[i] = s[tid] - v;
    if (tid == SCAN_B - 1) g_bsum[blockIdx.x] = s[tid];
}

__global__ void k_scan2() {
    __shared__ int s[64];
    int tid = threadIdx.x;
    int v = (tid < NBLK) ? g_bsum[tid] : 0;
    s[tid] = v;
    __syncthreads();
    #pragma unroll
    for (int off = 1; off < 64; off <<= 1) {
        int t = (tid >= off) ? s[tid - off] : 0;
        __syncthreads();
        s[tid] += t;
        __syncthreads();
    }
    if (tid < NBLK) g_bsum[tid] = s[tid] - v;
    if (tid == 0) g_off[NN] = EE;
}

__global__ void k_scan3() {
    int i = blockIdx.x * blockDim.x + threadIdx.x;
    if (i < NN) {
        int o = g_off[i] + g_bsum[i / SCAN_B];
        g_off[i] = o;
        g_cursor[i] = o;
    }
}

__global__ void k_scatter(const int* __restrict__ src, const int* __restrict__ dst,
                          const float* __restrict__ w) {
    int e = blockIdx.x * blockDim.x + threadIdx.x;
    if (e >= EE) return;
    int t = dst[e];
    int pos = atomicAdd(&g_cursor[t], 1);
    g_edge[pos] = make_float2(__int_as_float(src[e]), w[e]);
}

// ---------------------------------------------------------------------------
// K_agg_out: one warp per node, both batches, edge loop unrolled x2.
// Online softmax with joint (pairwise) max update; W_out loaded AFTER loop.
// ---------------------------------------------------------------------------
__device__ __forceinline__ float lk(float v) { return (v > 0.f) ? v : 0.1f * v; }

__global__ void __launch_bounds__(256) k_agg_out(
        const float* __restrict__ Wout, const float* __restrict__ bout,
        float* __restrict__ out) {
    __shared__ float sA[8][128];
    int warp = threadIdx.x >> 5;
    int lane = threadIdx.x & 31;
    int n = blockIdx.x * 8 + warp;
    if (n >= NN) return;

    int h0sel = lane >> 4;
    float4 e0 = *(const float4*)&g_er[n * 8];
    float4 e1 = *(const float4*)&g_er[n * 8 + 4];
    float er00 = h0sel ? e0.y : e0.x;
    float er01 = h0sel ? e0.w : e0.z;
    float er10 = h0sel ? e1.y : e1.x;
    float er11 = h0sel ? e1.w : e1.z;

    int beg = g_off[n], end = g_off[n + 1];

    float m00 = -3.0e38f, m01 = -3.0e38f, m10 = -3.0e38f, m11 = -3.0e38f;
    float d00 = 0.f, d01 = 0.f, d10 = 0.f, d11 = 0.f;
    float a0 = 0.f, a1 = 0.f, a2 = 0.f, a3 = 0.f;

    int e = beg;
    for (; e + 1 < end; e += 2) {
        // two independent edge chains in flight
        float2 edA = __ldg(&g_edge[e]);
        float2 edB = __ldg(&g_edge[e + 1]);
        int   sa = __float_as_int(edA.x);
        int   sb = __float_as_int(edB.x);
        float wa = edA.y, wb = edB.y;

        const float4* lpa = (const float4*)&g_el[sa * 8];
        const float4* lpb = (const float4*)&g_el[sb * 8];
        float4 la0 = __ldg(lpa), la1 = __ldg(lpa + 1);
        float4 lb0 = __ldg(lpb), lb1 = __ldg(lpb + 1);
        const float* fpa = &g_feat[sa * 128];
        const float* fpb = &g_feat[sb * 128];
        float fa0 = __ldg(fpa + lane);
        float fa1 = __ldg(fpa + 32 + lane);
        float fa2 = __ldg(fpa + 64 + lane);
        float fa3 = __ldg(fpa + 96 + lane);
        float fb0 = __ldg(fpb + lane);
        float fb1 = __ldg(fpb + 32 + lane);
        float fb2 = __ldg(fpb + 64 + lane);
        float fb3 = __ldg(fpb + 96 + lane);

        float sA00 = lk((h0sel ? la0.y : la0.x) + er00) * wa;
        float sA01 = lk((h0sel ? la0.w : la0.z) + er01) * wa;
        float sA10 = lk((h0sel ? la1.y : la1.x) + er10) * wa;
        float sA11 = lk((h0sel ? la1.w : la1.z) + er11) * wa;
        float sB00 = lk((h0sel ? lb0.y : lb0.x) + er00) * wb;
        float sB01 = lk((h0sel ? lb0.w : lb0.z) + er01) * wb;
        float sB10 = lk((h0sel ? lb1.y : lb1.x) + er10) * wb;
        float sB11 = lk((h0sel ? lb1.w : lb1.z) + er11) * wb;

        // chain 00
        { float mp = fmaxf(sA00, sB00);
          if (mp > m00) { float r = __expf(m00 - mp); d00 *= r; a0 *= r; m00 = mp; }
          float xa = __expf(sA00 - m00), xb = __expf(sB00 - m00);
          d00 += xa + xb; a0 += xa * fa0 + xb * fb0; }
        // chain 01
        { float mp = fmaxf(sA01, sB01);
          if (mp > m01) { float r = __expf(m01 - mp); d01 *= r; a1 *= r; m01 = mp; }
          float xa = __expf(sA01 - m01), xb = __expf(sB01 - m01);
          d01 += xa + xb; a1 += xa * fa1 + xb * fb1; }
        // chain 10
        { float mp = fmaxf(sA10, sB10);
          if (mp > m10) { float r = __expf(m10 - mp); d10 *= r; a2 *= r; m10 = mp; }
          float xa = __expf(sA10 - m10), xb = __expf(sB10 - m10);
          d10 += xa + xb; a2 += xa * fa2 + xb * fb2; }
        // chain 11
        { float mp = fmaxf(sA11, sB11);
          if (mp > m11) { float r = __expf(m11 - mp); d11 *= r; a3 *= r; m11 = mp; }
          float xa = __expf(sA11 - m11), xb = __expf(sB11 - m11);
          d11 += xa + xb; a3 += xa * fa3 + xb * fb3; }
    }
    if (e < end) {                       // tail edge
        float2 ed = __ldg(&g_edge[e]);
        int   s  = __float_as_int(ed.x);
        float we = ed.y;
        const float4* lp = (const float4*)&g_el[s * 8];
        float4 l0 = __ldg(lp), l1 = __ldg(lp + 1);
        const float* fp = &g_feat[s * 128];
        float f0 = __ldg(fp + lane);
        float f1 = __ldg(fp + 32 + lane);
        float f2 = __ldg(fp + 64 + lane);
        float f3 = __ldg(fp + 96 + lane);
        float sc00 = lk((h0sel ? l0.y : l0.x) + er00) * we;
        float sc01 = lk((h0sel ? l0.w : l0.z) + er01) * we;
        float sc10 = lk((h0sel ? l1.y : l1.x) + er10) * we;
        float sc11 = lk((h0sel ? l1.w : l1.z) + er11) * we;
        if (sc00 > m00) { float r = __expf(m00 - sc00); d00 *= r; a0 *= r; m00 = sc00; }
        if (sc01 > m01) { float r = __expf(m01 - sc01); d01 *= r; a1 *= r; m01 = sc01; }
        if (sc10 > m10) { float r = __expf(m10 - sc10); d10 *= r; a2 *= r; m10 = sc10; }
        if (sc11 > m11) { float r = __expf(m11 - sc11); d11 *= r; a3 *= r; m11 = sc11; }
        float x00 = __expf(sc00 - m00);
        float x01 = __expf(sc01 - m01);
        float x10 = __expf(sc10 - m10);
        float x11 = __expf(sc11 - m11);
        d00 += x00; d01 += x01; d10 += x10; d11 += x11;
        a0 += x00 * f0; a1 += x01 * f1; a2 += x10 * f2; a3 += x11 * f3;
    }

    float i00 = (d00 > 0.f) ? 1.f / d00 : 0.f;
    float i01 = (d01 > 0.f) ? 1.f / d01 : 0.f;
    float i10 = (d10 > 0.f) ? 1.f / d10 : 0.f;
    float i11 = (d11 > 0.f) ? 1.f / d11 : 0.f;
    sA[warp][lane]      = a0 * i00;
    sA[warp][32 + lane] = a1 * i01;
    sA[warp][64 + lane] = a2 * i10;
    sA[warp][96 + lane] = a3 * i11;
    __syncwarp();

    // W_out rows loaded only now (kept out of the hot loop's live range)
    float4 wA[4], wB[4];
    #pragma unroll
    for (int q = 0; q < 4; q++) {
        wA[q] = __ldg(&((const float4*)&Wout[lane * 16])[q]);
        wB[q] = __ldg(&((const float4*)&Wout[(lane + 32) * 16])[q]);
    }
    float bias0 = __ldg(&bout[lane]), bias1 = __ldg(&bout[lane + 32]);

    #pragma unroll
    for (int b = 0; b < 2; b++) {
        #pragma unroll
        for (int h = 0; h < 4; h++) {
            const float4* ap = (const float4*)&sA[warp][b * 64 + h * 16];
            float acc0 = bias0, acc1 = bias1;
            #pragma unroll
            for (int q = 0; q < 4; q++) {
                float4 av = ap[q];
                acc0 += av.x * wA[q].x + av.y * wA[q].y + av.z * wA[q].z + av.w * wA[q].w;
                acc1 += av.x * wB[q].x + av.y * wB[q].y + av.z * wB[q].z + av.w * wB[q].w;
            }
            float* op = &out[((b * NN + n) * 4 + h) * 64];
            op[lane]      = acc0;
            op[lane + 32] = acc1;
        }
    }
}

// ---------------------------------------------------------------------------
// inputs: vt, x, w, src, dst, W_fc, attn_l, attn_r, W_out, b_out
// ---------------------------------------------------------------------------
extern "C" void kernel_launch(void* const* d_in, const int* in_sizes, int n_in,
                              void* d_out, int out_size) {
    const float* x    = (const float*)d_in[1];
    const float* w    = (const float*)d_in[2];
    const int*   src  = (const int*)  d_in[3];
    const int*   dst  = (const int*)  d_in[4];
    const float* Wfc  = (const float*)d_in[5];
    const float* al   = (const float*)d_in[6];
    const float* ar   = (const float*)d_in[7];
    const float* Wout = (const float*)d_in[8];
    const float* bout = (const float*)d_in[9];
    float* out = (float*)d_out;

    k_feat<<<NB / 4, 256>>>(x, Wfc, al, ar);
    k_zero_deg<<<(NN + 255) / 256, 256>>>();
    k_count<<<(EE + 255) / 256, 256>>>(dst);
    k_scan1<<<NBLK, SCAN_B>>>();
    k_scan2<<<1, 64>>>();
    k_scan3<<<(NN + 255) / 256, 256>>>();
    k_scatter<<<(EE + 255) / 256, 256>>>(src, dst, w);
    k_agg_out<<<(NN + 7) / 8, 256>>>(Wout, bout, out);
}